// round 5
// baseline (speedup 1.0000x reference)
#include <cuda_runtime.h>
#include <math.h>

#define SEQ 4096
#define NH 12
#define HD 64
#define DIMM 768
#define QKV_LD 2304

// Scratch (allocation-free rule: __device__ globals)
__device__ float g_qkv[SEQ * QKV_LD];   // [t][comp*768 + h*64 + d]
__device__ float g_y[SEQ * DIMM];       // attention output [t][h*64+d]
__device__ float g_cos[SEQ * 32];
__device__ float g_sin[SEQ * 32];

// ---------------------------------------------------------------------------
// Rotary tables: freqs = (1/1024)^linspace(0,1,16) ++ zeros(16); theta = t*f
// computed to match the fp32 reference (theta rounded to fp32, trig in double)
// ---------------------------------------------------------------------------
__global__ void rotary_tables_kernel() {
    int t = blockIdx.x;
    int j = threadIdx.x;  // 0..31
    float freq = 0.0f;
    if (j < 16) freq = (float)pow(1.0 / 1024.0, (double)j * (1.0 / 15.0));
    float theta = (float)t * freq;
    g_cos[t * 32 + j] = (float)cos((double)theta);
    g_sin[t * 32 + j] = (float)sin((double)theta);
}

// ---------------------------------------------------------------------------
// Generic NT GEMM: C[m][n] = sum_k A[m*K+k] * B[n*K+k]
// A row-major [M,K], B row-major [N,K], C row-major [M,N]
// 128x128 tile, BK=16, 256 threads, 8x8 per-thread microtile.
// ---------------------------------------------------------------------------
__global__ __launch_bounds__(256) void gemm_nt_kernel(
    const float* __restrict__ A, const float* __restrict__ B,
    float* __restrict__ C, int M, int N, int K)
{
    __shared__ float As[16][128];
    __shared__ float Bs[16][128];
    int bm = blockIdx.y * 128;
    int bn = blockIdx.x * 128;
    int tid = threadIdx.x;
    int tx = tid & 15;       // 0..15  (n dir)
    int ty = tid >> 4;       // 0..15  (m dir)

    float acc[8][8];
#pragma unroll
    for (int i = 0; i < 8; i++)
#pragma unroll
        for (int j = 0; j < 8; j++) acc[i][j] = 0.0f;

    for (int k0 = 0; k0 < K; k0 += 16) {
#pragma unroll
        for (int l = 0; l < 2; l++) {
            int li = tid + l * 256;          // 0..511
            int row = li >> 2;               // 0..127
            int c4  = li & 3;                // 0..3
            float4 va = *(const float4*)(A + (size_t)(bm + row) * K + k0 + c4 * 4);
            As[c4 * 4 + 0][row] = va.x;
            As[c4 * 4 + 1][row] = va.y;
            As[c4 * 4 + 2][row] = va.z;
            As[c4 * 4 + 3][row] = va.w;
            float4 vb = *(const float4*)(B + (size_t)(bn + row) * K + k0 + c4 * 4);
            Bs[c4 * 4 + 0][row] = vb.x;
            Bs[c4 * 4 + 1][row] = vb.y;
            Bs[c4 * 4 + 2][row] = vb.z;
            Bs[c4 * 4 + 3][row] = vb.w;
        }
        __syncthreads();
#pragma unroll
        for (int kk = 0; kk < 16; kk++) {
            float a[8], b[8];
            *(float4*)&a[0] = *(const float4*)&As[kk][ty * 8];
            *(float4*)&a[4] = *(const float4*)&As[kk][ty * 8 + 4];
            *(float4*)&b[0] = *(const float4*)&Bs[kk][tx * 8];
            *(float4*)&b[4] = *(const float4*)&Bs[kk][tx * 8 + 4];
#pragma unroll
            for (int i = 0; i < 8; i++)
#pragma unroll
                for (int j = 0; j < 8; j++)
                    acc[i][j] += a[i] * b[j];
        }
        __syncthreads();
    }

#pragma unroll
    for (int i = 0; i < 8; i++) {
        int row = bm + ty * 8 + i;
        float* cp = C + (size_t)row * N + bn + tx * 8;
        *(float4*)cp       = make_float4(acc[i][0], acc[i][1], acc[i][2], acc[i][3]);
        *(float4*)(cp + 4) = make_float4(acc[i][4], acc[i][5], acc[i][6], acc[i][7]);
    }
}

// ---------------------------------------------------------------------------
// Fused RMSNorm (per head, D=64) + rotary for q and k, in place on g_qkv.
// One warp per (t, h, comp). 8 warps per block.
// ---------------------------------------------------------------------------
__global__ __launch_bounds__(256) void rmsrot_kernel() {
    int task = blockIdx.x * 8 + (threadIdx.x >> 5);  // 0 .. 4096*12*2-1
    int lane = threadIdx.x & 31;
    int c = task & 1;             // 0 = q, 1 = k
    int h = (task >> 1) % NH;
    int t = task / (2 * NH);

    float* p = g_qkv + (size_t)t * QKV_LD + c * DIMM + h * HD;
    float x0 = p[lane];
    float x1 = p[lane + 32];
    float ss = x0 * x0 + x1 * x1;
#pragma unroll
    for (int off = 16; off > 0; off >>= 1)
        ss += __shfl_xor_sync(0xffffffffu, ss, off);
    float r = rsqrtf(ss * (1.0f / 64.0f) + 1.1920928955078125e-07f);
    x0 *= r;
    x1 *= r;
    float cv = g_cos[t * 32 + lane];
    float sv = g_sin[t * 32 + lane];
    p[lane]      =  x0 * cv + x1 * sv;
    p[lane + 32] = -x0 * sv + x1 * cv;
}

// ---------------------------------------------------------------------------
// Flash attention, fp32.  CTA = (64-row q-block, head). 256 threads.
// smem tiles stored transposed [k][row] so both GEMM phases read float4
// broadcast/conflict-free.
// ---------------------------------------------------------------------------
#define FLD 68
#define FLASH_SMEM ((5 * 64 * FLD + 64) * 4)

__global__ __launch_bounds__(256) void flash_kernel() {
    extern __shared__ float sm[];
    float* QT = sm;                 // [64 k][FLD rows]
    float* KT = QT + 64 * FLD;      // [64 k][FLD cols]
    float* Vs = KT + 64 * FLD;      // [64 j][FLD d]
    float* Ss = Vs + 64 * FLD;      // [64 r][FLD c]
    float* PT = Ss + 64 * FLD;      // [64 c][FLD r]
    float* cr = PT + 64 * FLD;      // [64] corr factors, then final l

    int qb = blockIdx.x;            // q block (64 rows)
    int h  = blockIdx.y;            // head
    int tid = threadIdx.x;
    int lane = tid & 31;
    int w = tid >> 5;
    int tx = tid & 15;              // col dir
    int ty = tid >> 4;              // row dir

    // load Q tile transposed
    const float* qbase = g_qkv + (size_t)(qb * 64) * QKV_LD + h * HD;
    for (int idx = tid; idx < 64 * 64; idx += 256) {
        int t = idx >> 6, d = idx & 63;
        QT[d * FLD + t] = qbase[t * QKV_LD + d];
    }

    float m_i[8], l_i[8];
#pragma unroll
    for (int rrr = 0; rrr < 8; rrr++) { m_i[rrr] = -INFINITY; l_i[rrr] = 0.0f; }
    float o[4][4];
#pragma unroll
    for (int i = 0; i < 4; i++)
#pragma unroll
        for (int j = 0; j < 4; j++) o[i][j] = 0.0f;

    const float* kb = g_qkv + DIMM + h * HD;
    const float* vb = g_qkv + 2 * DIMM + h * HD;

    for (int kt = 0; kt <= qb; kt++) {
        __syncthreads();  // prev PV done (Vs, PT, cr reusable); also covers Q store on iter 0
        int t0 = kt * 64;
        for (int idx = tid; idx < 64 * 64; idx += 256) {
            int t = idx >> 6, d = idx & 63;
            size_t g = (size_t)(t0 + t) * QKV_LD + d;
            KT[d * FLD + t] = kb[g];
            Vs[t * FLD + d] = vb[g];
        }
        __syncthreads();

        // ---- S = Q K^T (scaled, masked) ----
        float acc[4][4];
#pragma unroll
        for (int i = 0; i < 4; i++)
#pragma unroll
            for (int j = 0; j < 4; j++) acc[i][j] = 0.0f;
#pragma unroll 8
        for (int kk = 0; kk < 64; kk++) {
            float a[4], b[4];
            *(float4*)a = *(const float4*)&QT[kk * FLD + ty * 4];
            *(float4*)b = *(const float4*)&KT[kk * FLD + tx * 4];
#pragma unroll
            for (int i = 0; i < 4; i++)
#pragma unroll
                for (int j = 0; j < 4; j++)
                    acc[i][j] += a[i] * b[j];
        }
        int grow = qb * 64;
#pragma unroll
        for (int i = 0; i < 4; i++) {
            int r = ty * 4 + i;
            float sv[4];
#pragma unroll
            for (int j = 0; j < 4; j++) {
                int c = tx * 4 + j;
                float v = acc[i][j] * 0.12f;
                if (t0 + c > grow + r) v = -3.0e38f;
                sv[j] = v;
            }
            *(float4*)&Ss[r * FLD + tx * 4] = make_float4(sv[0], sv[1], sv[2], sv[3]);
        }
        __syncthreads();

        // ---- online softmax: warp w owns rows w*8 .. w*8+7 ----
#pragma unroll
        for (int rr = 0; rr < 8; rr++) {
            int r = w * 8 + rr;
            float s0 = Ss[r * FLD + lane];
            float s1 = Ss[r * FLD + 32 + lane];
            float mt = fmaxf(s0, s1);
#pragma unroll
            for (int off = 16; off > 0; off >>= 1)
                mt = fmaxf(mt, __shfl_xor_sync(0xffffffffu, mt, off));
            float m_new = fmaxf(m_i[rr], mt);
            float corr = expf(m_i[rr] - m_new);
            float p0 = expf(s0 - m_new);
            float p1 = expf(s1 - m_new);
            float ps = p0 + p1;
#pragma unroll
            for (int off = 16; off > 0; off >>= 1)
                ps += __shfl_xor_sync(0xffffffffu, ps, off);
            l_i[rr] = l_i[rr] * corr + ps;
            m_i[rr] = m_new;
            PT[lane * FLD + r] = p0;
            PT[(lane + 32) * FLD + r] = p1;
            if (lane == 0) cr[r] = corr;
        }
        __syncthreads();

        // ---- O = O*corr + P V ----
        float ci[4];
#pragma unroll
        for (int i = 0; i < 4; i++) ci[i] = cr[ty * 4 + i];
#pragma unroll
        for (int i = 0; i < 4; i++)
#pragma unroll
            for (int j = 0; j < 4; j++) o[i][j] *= ci[i];
#pragma unroll 8
        for (int kk = 0; kk < 64; kk++) {
            float a[4], b[4];
            *(float4*)a = *(const float4*)&PT[kk * FLD + ty * 4];
            *(float4*)b = *(const float4*)&Vs[kk * FLD + tx * 4];
#pragma unroll
            for (int i = 0; i < 4; i++)
#pragma unroll
                for (int j = 0; j < 4; j++)
                    o[i][j] += a[i] * b[j];
        }
    }

    // epilogue: publish l, normalize, store
    __syncthreads();
#pragma unroll
    for (int rr = 0; rr < 8; rr++)
        if (lane == 0) cr[w * 8 + rr] = l_i[rr];
    __syncthreads();
#pragma unroll
    for (int i = 0; i < 4; i++) {
        int r = ty * 4 + i;
        float inv = 1.0f / cr[r];
        int t = qb * 64 + r;
        float4 v = make_float4(o[i][0] * inv, o[i][1] * inv, o[i][2] * inv, o[i][3] * inv);
        *(float4*)&g_y[(size_t)t * DIMM + h * HD + tx * 4] = v;
    }
}

// ---------------------------------------------------------------------------
extern "C" void kernel_launch(void* const* d_in, const int* in_sizes, int n_in,
                              void* d_out, int out_size) {
    const float* x        = (const float*)d_in[0];   // [1,4096,768]
    const float* qkv_w    = (const float*)d_in[1];   // [3,768,768] = [N=2304][K=768]
    const float* c_proj_w = (const float*)d_in[2];   // [768,768]
    float* out = (float*)d_out;                      // [1,4096,768]

    float *qkv_p, *y_p;
    cudaGetSymbolAddress((void**)&qkv_p, g_qkv);
    cudaGetSymbolAddress((void**)&y_p, g_y);

    cudaFuncSetAttribute(flash_kernel, cudaFuncAttributeMaxDynamicSharedMemorySize,
                         FLASH_SMEM);

    // 1. rotary tables
    rotary_tables_kernel<<<SEQ, 32>>>();
    // 2. QKV projection: [4096,768] x [2304,768]^T -> [4096,2304]
    gemm_nt_kernel<<<dim3(QKV_LD / 128, SEQ / 128), 256>>>(x, qkv_w, qkv_p,
                                                           SEQ, QKV_LD, DIMM);
    // 3. RMSNorm + rotary on q,k
    rmsrot_kernel<<<SEQ * NH * 2 / 8, 256>>>();
    // 4. causal flash attention
    flash_kernel<<<dim3(SEQ / 64, NH), 256, FLASH_SMEM>>>();
    // 5. output projection: [4096,768] x [768,768]^T -> out
    gemm_nt_kernel<<<dim3(DIMM / 128, SEQ / 128), 256>>>(y_p, c_proj_w, out,
                                                         SEQ, DIMM, DIMM);
}

// round 7
// speedup vs baseline: 1.1353x; 1.1353x over previous
#include <cuda_runtime.h>
#include <math.h>

#define SEQ 4096
#define NH 12
#define HD 64
#define DIMM 768
#define QKV_LD 2304
typedef unsigned long long ull;

// Scratch (allocation-free rule: __device__ globals)
__device__ float g_qkv[SEQ * QKV_LD];   // [t][comp*768 + h*64 + d]
__device__ float g_y[SEQ * DIMM];       // attention output [t][h*64+d]
__device__ float g_cos[SEQ * 32];
__device__ float g_sin[SEQ * 32];

// ---- packed f32x2 helpers (sm_103a FFMA2 path; ptxas never auto-fuses) ----
__device__ __forceinline__ ull f2dup(float x) {
    ull r; asm("mov.b64 %0, {%1, %1};" : "=l"(r) : "f"(x)); return r;
}
__device__ __forceinline__ ull f2pack(float lo, float hi) {
    ull r; asm("mov.b64 %0, {%1, %2};" : "=l"(r) : "f"(lo), "f"(hi)); return r;
}
__device__ __forceinline__ void f2unpack(ull v, float& lo, float& hi) {
    asm("mov.b64 {%0, %1}, %2;" : "=f"(lo), "=f"(hi) : "l"(v));
}
__device__ __forceinline__ void ffma2(ull& d, ull a, ull b) {
    asm("fma.rn.f32x2 %0, %1, %2, %0;" : "+l"(d) : "l"(a), "l"(b));
}
__device__ __forceinline__ void fmul2(ull& d, ull c) {
    asm("mul.rn.f32x2 %0, %0, %1;" : "+l"(d) : "l"(c));
}

// ---------------------------------------------------------------------------
// Rotary tables: freqs = (1/1024)^linspace(0,1,16) ++ zeros(16); theta = t*f
// ---------------------------------------------------------------------------
__global__ void rotary_tables_kernel() {
    int t = blockIdx.x;
    int j = threadIdx.x;  // 0..31
    float freq = 0.0f;
    if (j < 16) freq = (float)pow(1.0 / 1024.0, (double)j * (1.0 / 15.0));
    float theta = (float)t * freq;
    g_cos[t * 32 + j] = (float)cos((double)theta);
    g_sin[t * 32 + j] = (float)sin((double)theta);
}

// ---------------------------------------------------------------------------
// NT GEMM with FFMA2: C[m][n] = sum_k A[m*K+k]*B[n*K+k]
// 128x128 tile, BK=16, 256 threads, 8x8 microtile as 4 row-pairs x 8 cols.
// Row-pairs load straight from transposed smem as 8-byte LDS (no pack).
// ---------------------------------------------------------------------------
__global__ __launch_bounds__(256, 2) void gemm_nt_kernel(
    const float* __restrict__ A, const float* __restrict__ B,
    float* __restrict__ C, int M, int N, int K)
{
    __shared__ float As[16][128];
    __shared__ float Bs[16][128];
    int bm = blockIdx.y * 128;
    int bn = blockIdx.x * 128;
    int tid = threadIdx.x;
    int tx = tid & 15;       // n dir
    int ty = tid >> 4;       // m dir

    ull acc2[4][8];
#pragma unroll
    for (int p = 0; p < 4; p++)
#pragma unroll
        for (int j = 0; j < 8; j++) acc2[p][j] = 0ull;

    for (int k0 = 0; k0 < K; k0 += 16) {
#pragma unroll
        for (int l = 0; l < 2; l++) {
            int li = tid + l * 256;          // 0..511
            int row = li >> 2;               // 0..127
            int c4  = li & 3;                // 0..3
            float4 va = *(const float4*)(A + (size_t)(bm + row) * K + k0 + c4 * 4);
            As[c4 * 4 + 0][row] = va.x;
            As[c4 * 4 + 1][row] = va.y;
            As[c4 * 4 + 2][row] = va.z;
            As[c4 * 4 + 3][row] = va.w;
            float4 vb = *(const float4*)(B + (size_t)(bn + row) * K + k0 + c4 * 4);
            Bs[c4 * 4 + 0][row] = vb.x;
            Bs[c4 * 4 + 1][row] = vb.y;
            Bs[c4 * 4 + 2][row] = vb.z;
            Bs[c4 * 4 + 3][row] = vb.w;
        }
        __syncthreads();
#pragma unroll
        for (int kk = 0; kk < 16; kk++) {
            const ull* ap = (const ull*)&As[kk][ty * 8];
            ull a0 = ap[0], a1 = ap[1], a2 = ap[2], a3 = ap[3];
            float4 b0 = *(const float4*)&Bs[kk][tx * 8];
            float4 b1 = *(const float4*)&Bs[kk][tx * 8 + 4];
            ull bd[8];
            bd[0] = f2dup(b0.x); bd[1] = f2dup(b0.y);
            bd[2] = f2dup(b0.z); bd[3] = f2dup(b0.w);
            bd[4] = f2dup(b1.x); bd[5] = f2dup(b1.y);
            bd[6] = f2dup(b1.z); bd[7] = f2dup(b1.w);
#pragma unroll
            for (int j = 0; j < 8; j++) {
                ffma2(acc2[0][j], a0, bd[j]);
                ffma2(acc2[1][j], a1, bd[j]);
                ffma2(acc2[2][j], a2, bd[j]);
                ffma2(acc2[3][j], a3, bd[j]);
            }
        }
        __syncthreads();
    }

#pragma unroll
    for (int p = 0; p < 4; p++) {
        float lo[8], hi[8];
#pragma unroll
        for (int j = 0; j < 8; j++) f2unpack(acc2[p][j], lo[j], hi[j]);
        float* c0 = C + (size_t)(bm + ty * 8 + 2 * p) * N + bn + tx * 8;
        float* c1 = C + (size_t)(bm + ty * 8 + 2 * p + 1) * N + bn + tx * 8;
        *(float4*)c0       = make_float4(lo[0], lo[1], lo[2], lo[3]);
        *(float4*)(c0 + 4) = make_float4(lo[4], lo[5], lo[6], lo[7]);
        *(float4*)c1       = make_float4(hi[0], hi[1], hi[2], hi[3]);
        *(float4*)(c1 + 4) = make_float4(hi[4], hi[5], hi[6], hi[7]);
    }
}

// ---------------------------------------------------------------------------
// Fused RMSNorm (per head, D=64) + rotary for q and k, in place on g_qkv.
// ---------------------------------------------------------------------------
__global__ __launch_bounds__(256) void rmsrot_kernel() {
    int task = blockIdx.x * 8 + (threadIdx.x >> 5);
    int lane = threadIdx.x & 31;
    int c = task & 1;
    int h = (task >> 1) % NH;
    int t = task / (2 * NH);

    float* p = g_qkv + (size_t)t * QKV_LD + c * DIMM + h * HD;
    float x0 = p[lane];
    float x1 = p[lane + 32];
    float ss = x0 * x0 + x1 * x1;
#pragma unroll
    for (int off = 16; off > 0; off >>= 1)
        ss += __shfl_xor_sync(0xffffffffu, ss, off);
    float r = rsqrtf(ss * (1.0f / 64.0f) + 1.1920928955078125e-07f);
    x0 *= r;
    x1 *= r;
    float cv = g_cos[t * 32 + lane];
    float sv = g_sin[t * 32 + lane];
    p[lane]      =  x0 * cv + x1 * sv;
    p[lane + 32] = -x0 * sv + x1 * cv;
}

// ---------------------------------------------------------------------------
// Flash attention, fp32 FFMA2. CTA = (128-row q-block, head). 256 threads.
// S tile 128x64, microtile 8 rows x 4 cols (row-pairs packed in f32x2).
// Softmax fully in registers (16-lane shfl groups); P transposed to smem
// for the PV GEMM. smem ~102KB -> 2 CTAs/SM.
// ---------------------------------------------------------------------------
#define FQ 130
#define FK 68
#define FP 132
#define FLASH_SMEM ((64 * FQ + 64 * FK + 64 * FK + 64 * FP) * 4)

__global__ __launch_bounds__(256, 2) void flash_kernel() {
    extern __shared__ float sm[];
    float* QT = sm;                    // [64 d][FQ rows(128)]
    float* KT = QT + 64 * FQ;          // [64 d][FK cols(64)]
    float* Vs = KT + 64 * FK;          // [64 kv][FK d(64)]
    float* PT = Vs + 64 * FK;          // [64 kv][FP rows(128)]

    int qb = (SEQ / 128 - 1) - blockIdx.x;   // largest q-blocks first
    int h  = blockIdx.y;
    int tid = threadIdx.x;
    int tx = tid & 15;              // col dir (4 cols each)
    int ty = tid >> 4;              // row dir (8 rows each)

    // load Q tile transposed: rows qb*128..+127
    const float* qbase = g_qkv + (size_t)(qb * 128) * QKV_LD + h * HD;
    for (int idx = tid; idx < 128 * 64; idx += 256) {
        int t = idx >> 6, d = idx & 63;
        QT[d * FQ + t] = qbase[t * QKV_LD + d];
    }

    float m_pr[8], l_i[8];
#pragma unroll
    for (int i = 0; i < 8; i++) { m_pr[i] = -INFINITY; l_i[i] = 0.0f; }
    ull o2[4][4];
#pragma unroll
    for (int p = 0; p < 4; p++)
#pragma unroll
        for (int j = 0; j < 4; j++) o2[p][j] = 0ull;

    const float* kb = g_qkv + DIMM + h * HD;
    const float* vb = g_qkv + 2 * DIMM + h * HD;

    int ktmax = 2 * qb + 1;
    for (int kt = 0; kt <= ktmax; kt++) {
        __syncthreads();  // prev PV done; also covers Q store on iter 0
        int t0 = kt * 64;
        for (int idx = tid; idx < 64 * 64; idx += 256) {
            int t = idx >> 6, d = idx & 63;
            size_t g = (size_t)(t0 + t) * QKV_LD + d;
            KT[d * FK + t] = kb[g];
            Vs[t * FK + d] = vb[g];
        }
        __syncthreads();

        // ---- S = Q K^T (row-pairs in f32x2) ----
        ull s2[4][4];
#pragma unroll
        for (int p = 0; p < 4; p++)
#pragma unroll
            for (int j = 0; j < 4; j++) s2[p][j] = 0ull;
#pragma unroll 4
        for (int kk = 0; kk < 64; kk++) {
            const ull* ap = (const ull*)&QT[kk * FQ + ty * 8];
            ull a0 = ap[0], a1 = ap[1], a2 = ap[2], a3 = ap[3];
            float4 bv = *(const float4*)&KT[kk * FK + tx * 4];
            ull b0 = f2dup(bv.x), b1 = f2dup(bv.y);
            ull b2 = f2dup(bv.z), b3 = f2dup(bv.w);
            ffma2(s2[0][0], a0, b0); ffma2(s2[0][1], a0, b1);
            ffma2(s2[0][2], a0, b2); ffma2(s2[0][3], a0, b3);
            ffma2(s2[1][0], a1, b0); ffma2(s2[1][1], a1, b1);
            ffma2(s2[1][2], a1, b2); ffma2(s2[1][3], a1, b3);
            ffma2(s2[2][0], a2, b0); ffma2(s2[2][1], a2, b1);
            ffma2(s2[2][2], a2, b2); ffma2(s2[2][3], a2, b3);
            ffma2(s2[3][0], a3, b0); ffma2(s2[3][1], a3, b1);
            ffma2(s2[3][2], a3, b2); ffma2(s2[3][3], a3, b3);
        }

        // ---- online softmax in registers (row group = 16 lanes of tx) ----
        bool msk = (kt >= 2 * qb);
        float pl[4][4], ph[4][4];
#pragma unroll
        for (int p = 0; p < 4; p++) {
            float slo[4], shi[4];
#pragma unroll
            for (int j = 0; j < 4; j++) {
                float lo, hi;
                f2unpack(s2[p][j], lo, hi);
                slo[j] = lo * 0.12f;
                shi[j] = hi * 0.12f;
            }
            if (msk) {
                int grl = qb * 128 + ty * 8 + 2 * p;
#pragma unroll
                for (int j = 0; j < 4; j++) {
                    int gc = t0 + tx * 4 + j;
                    if (gc > grl)     slo[j] = -3.0e38f;
                    if (gc > grl + 1) shi[j] = -3.0e38f;
                }
            }
            float ml = fmaxf(fmaxf(slo[0], slo[1]), fmaxf(slo[2], slo[3]));
            float mh = fmaxf(fmaxf(shi[0], shi[1]), fmaxf(shi[2], shi[3]));
#pragma unroll
            for (int off = 1; off < 16; off <<= 1) {
                ml = fmaxf(ml, __shfl_xor_sync(0xffffffffu, ml, off));
                mh = fmaxf(mh, __shfl_xor_sync(0xffffffffu, mh, off));
            }
            float mnl = fmaxf(m_pr[2 * p],     ml);
            float mnh = fmaxf(m_pr[2 * p + 1], mh);
            float cl = __expf(m_pr[2 * p]     - mnl);
            float ch = __expf(m_pr[2 * p + 1] - mnh);
            float sl = 0.0f, sh = 0.0f;
#pragma unroll
            for (int j = 0; j < 4; j++) {
                pl[p][j] = __expf(slo[j] - mnl); sl += pl[p][j];
                ph[p][j] = __expf(shi[j] - mnh); sh += ph[p][j];
            }
#pragma unroll
            for (int off = 1; off < 16; off <<= 1) {
                sl += __shfl_xor_sync(0xffffffffu, sl, off);
                sh += __shfl_xor_sync(0xffffffffu, sh, off);
            }
            l_i[2 * p]     = l_i[2 * p]     * cl + sl;
            l_i[2 * p + 1] = l_i[2 * p + 1] * ch + sh;
            m_pr[2 * p]     = mnl;
            m_pr[2 * p + 1] = mnh;
            ull c2 = f2pack(cl, ch);
            fmul2(o2[p][0], c2); fmul2(o2[p][1], c2);
            fmul2(o2[p][2], c2); fmul2(o2[p][3], c2);
        }

        // ---- write P transposed ----
#pragma unroll
        for (int j = 0; j < 4; j++) {
            int c = tx * 4 + j;
            *(float4*)&PT[c * FP + ty * 8] =
                make_float4(pl[0][j], ph[0][j], pl[1][j], ph[1][j]);
            *(float4*)&PT[c * FP + ty * 8 + 4] =
                make_float4(pl[2][j], ph[2][j], pl[3][j], ph[3][j]);
        }
        __syncthreads();

        // ---- O += P V ----
#pragma unroll 4
        for (int kk = 0; kk < 64; kk++) {
            const ull* ap = (const ull*)&PT[kk * FP + ty * 8];
            ull a0 = ap[0], a1 = ap[1], a2 = ap[2], a3 = ap[3];
            float4 bv = *(const float4*)&Vs[kk * FK + tx * 4];
            ull b0 = f2dup(bv.x), b1 = f2dup(bv.y);
            ull b2 = f2dup(bv.z), b3 = f2dup(bv.w);
            ffma2(o2[0][0], a0, b0); ffma2(o2[0][1], a0, b1);
            ffma2(o2[0][2], a0, b2); ffma2(o2[0][3], a0, b3);
            ffma2(o2[1][0], a1, b0); ffma2(o2[1][1], a1, b1);
            ffma2(o2[1][2], a1, b2); ffma2(o2[1][3], a1, b3);
            ffma2(o2[2][0], a2, b0); ffma2(o2[2][1], a2, b1);
            ffma2(o2[2][2], a2, b2); ffma2(o2[2][3], a2, b3);
            ffma2(o2[3][0], a3, b0); ffma2(o2[3][1], a3, b1);
            ffma2(o2[3][2], a3, b2); ffma2(o2[3][3], a3, b3);
        }
    }

    // ---- epilogue: normalize, store ----
#pragma unroll
    for (int p = 0; p < 4; p++) {
        ull iv = f2pack(1.0f / l_i[2 * p], 1.0f / l_i[2 * p + 1]);
        fmul2(o2[p][0], iv); fmul2(o2[p][1], iv);
        fmul2(o2[p][2], iv); fmul2(o2[p][3], iv);
        float lo[4], hi[4];
#pragma unroll
        for (int j = 0; j < 4; j++) f2unpack(o2[p][j], lo[j], hi[j]);
        int t = qb * 128 + ty * 8 + 2 * p;
        *(float4*)&g_y[(size_t)t * DIMM + h * HD + tx * 4] =
            make_float4(lo[0], lo[1], lo[2], lo[3]);
        *(float4*)&g_y[(size_t)(t + 1) * DIMM + h * HD + tx * 4] =
            make_float4(hi[0], hi[1], hi[2], hi[3]);
    }
}

// ---------------------------------------------------------------------------
extern "C" void kernel_launch(void* const* d_in, const int* in_sizes, int n_in,
                              void* d_out, int out_size) {
    const float* x        = (const float*)d_in[0];   // [1,4096,768]
    const float* qkv_w    = (const float*)d_in[1];   // [3,768,768] = [N=2304][K=768]
    const float* c_proj_w = (const float*)d_in[2];   // [768,768]
    float* out = (float*)d_out;                      // [1,4096,768]

    float *qkv_p, *y_p;
    cudaGetSymbolAddress((void**)&qkv_p, g_qkv);
    cudaGetSymbolAddress((void**)&y_p, g_y);

    cudaFuncSetAttribute(flash_kernel, cudaFuncAttributeMaxDynamicSharedMemorySize,
                         FLASH_SMEM);

    // 1. rotary tables
    rotary_tables_kernel<<<SEQ, 32>>>();
    // 2. QKV projection: [4096,768] x [2304,768]^T -> [4096,2304]
    gemm_nt_kernel<<<dim3(QKV_LD / 128, SEQ / 128), 256>>>(x, qkv_w, qkv_p,
                                                           SEQ, QKV_LD, DIMM);
    // 3. RMSNorm + rotary on q,k
    rmsrot_kernel<<<SEQ * NH * 2 / 8, 256>>>();
    // 4. causal flash attention (128-row q blocks)
    flash_kernel<<<dim3(SEQ / 128, NH), 256, FLASH_SMEM>>>();
    // 5. output projection: [4096,768] x [768,768]^T -> out
    gemm_nt_kernel<<<dim3(DIMM / 128, SEQ / 128), 256>>>(y_p, c_proj_w, out,
                                                         SEQ, DIMM, DIMM);
}

// round 12
// speedup vs baseline: 1.4162x; 1.2474x over previous
#include <cuda_runtime.h>
#include <math.h>
#include <cstdint>

#define SEQ 4096
#define NH 12
#define HD 64
#define DIMM 768
#define QKV_LD 2304
typedef unsigned long long ull;

// Scratch (allocation-free rule: __device__ globals)
__device__ float g_qkv[SEQ * QKV_LD];   // [t][comp*768 + h*64 + d]
__device__ float g_y[SEQ * DIMM];       // attention output [t][h*64+d]
__device__ float g_cos[SEQ * 32];
__device__ float g_sin[SEQ * 32];

// ---- packed f32x2 helpers ----
__device__ __forceinline__ ull f2dup(float x) {
    ull r; asm("mov.b64 %0, {%1, %1};" : "=l"(r) : "f"(x)); return r;
}
__device__ __forceinline__ ull f2pack(float lo, float hi) {
    ull r; asm("mov.b64 %0, {%1, %2};" : "=l"(r) : "f"(lo), "f"(hi)); return r;
}
__device__ __forceinline__ void f2unpack(ull v, float& lo, float& hi) {
    asm("mov.b64 {%0, %1}, %2;" : "=f"(lo), "=f"(hi) : "l"(v));
}
__device__ __forceinline__ void ffma2(ull& d, ull a, ull b) {
    asm("fma.rn.f32x2 %0, %1, %2, %0;" : "+l"(d) : "l"(a), "l"(b));
}
__device__ __forceinline__ void fmul2(ull& d, ull c) {
    asm("mul.rn.f32x2 %0, %0, %1;" : "+l"(d) : "l"(c));
}

__device__ __forceinline__ uint32_t to_tf32(float x) {
    uint32_t u;
    asm("cvt.rna.tf32.f32 %0, %1;" : "=r"(u) : "f"(x));
    return u;
}

// ---------------------------------------------------------------------------
// Rotary tables
// ---------------------------------------------------------------------------
__global__ void rotary_tables_kernel() {
    int t = blockIdx.x;
    int j = threadIdx.x;
    float freq = 0.0f;
    if (j < 16) freq = (float)pow(1.0 / 1024.0, (double)j * (1.0 / 15.0));
    float theta = (float)t * freq;
    g_cos[t * 32 + j] = (float)cos((double)theta);
    g_sin[t * 32 + j] = (float)sin((double)theta);
}

// ---------------------------------------------------------------------------
// tf32 warp-MMA NT GEMM: C[m][n] = sum_k A[m*K+k]*B[n*K+k]
// mma.sync.m16n8k8 (tensor pipe, generic PTX — no 'a' features).
// CTA 128x128, BK=32, 8 warps as 4(m)x2(n), warp tile 32x64 (2x8 mma tiles).
// smem pitch 36 floats -> fragment loads land on banks 4*g+tig: conflict-free.
// ---------------------------------------------------------------------------
__global__ __launch_bounds__(256) void gemm_mma_kernel(
    const float* __restrict__ A, const float* __restrict__ B,
    float* __restrict__ C, int M, int N, int K)
{
    __shared__ uint32_t As[128][36];
    __shared__ uint32_t Bs[128][36];
    int tid = threadIdx.x;
    int lane = tid & 31;
    int wid = tid >> 5;
    int g = lane >> 2;        // group id 0..7
    int tig = lane & 3;       // thread in group
    int bm = blockIdx.y * 128;
    int bn = blockIdx.x * 128;
    int wm = (wid & 3) * 32;  // warp m offset
    int wn = (wid >> 2) * 64; // warp n offset

    float acc[2][8][4];
#pragma unroll
    for (int mi = 0; mi < 2; mi++)
#pragma unroll
        for (int ni = 0; ni < 8; ni++)
#pragma unroll
            for (int r = 0; r < 4; r++) acc[mi][ni][r] = 0.0f;

    for (int k0 = 0; k0 < K; k0 += 32) {
        // stage A[128][32] and B[128][32] chunks, converting to tf32
        for (int i = tid; i < 1024; i += 256) {
            int row = i >> 3;
            int c4 = i & 7;
            float4 va = *(const float4*)(A + (size_t)(bm + row) * K + k0 + c4 * 4);
            *(uint4*)&As[row][c4 * 4] = make_uint4(
                to_tf32(va.x), to_tf32(va.y), to_tf32(va.z), to_tf32(va.w));
            float4 vb = *(const float4*)(B + (size_t)(bn + row) * K + k0 + c4 * 4);
            *(uint4*)&Bs[row][c4 * 4] = make_uint4(
                to_tf32(vb.x), to_tf32(vb.y), to_tf32(vb.z), to_tf32(vb.w));
        }
        __syncthreads();
#pragma unroll
        for (int s = 0; s < 4; s++) {
            int ks = s * 8;
            uint32_t af[2][4];
#pragma unroll
            for (int mi = 0; mi < 2; mi++) {
                int mr = wm + mi * 16 + g;
                af[mi][0] = As[mr][ks + tig];
                af[mi][1] = As[mr + 8][ks + tig];
                af[mi][2] = As[mr][ks + tig + 4];
                af[mi][3] = As[mr + 8][ks + tig + 4];
            }
#pragma unroll
            for (int ni = 0; ni < 8; ni++) {
                int nc = wn + ni * 8 + g;
                uint32_t b0 = Bs[nc][ks + tig];
                uint32_t b1 = Bs[nc][ks + tig + 4];
#pragma unroll
                for (int mi = 0; mi < 2; mi++) {
                    asm volatile(
                        "mma.sync.aligned.m16n8k8.row.col.f32.tf32.tf32.f32 "
                        "{%0,%1,%2,%3}, {%4,%5,%6,%7}, {%8,%9}, {%0,%1,%2,%3};"
                        : "+f"(acc[mi][ni][0]), "+f"(acc[mi][ni][1]),
                          "+f"(acc[mi][ni][2]), "+f"(acc[mi][ni][3])
                        : "r"(af[mi][0]), "r"(af[mi][1]),
                          "r"(af[mi][2]), "r"(af[mi][3]),
                          "r"(b0), "r"(b1));
                }
            }
        }
        __syncthreads();
    }

    // epilogue: d0,d1 @ (g, 2tig..2tig+1), d2,d3 @ (g+8, same)
#pragma unroll
    for (int mi = 0; mi < 2; mi++) {
#pragma unroll
        for (int ni = 0; ni < 8; ni++) {
            int row = bm + wm + mi * 16 + g;
            int col = bn + wn + ni * 8 + tig * 2;
            *(float2*)(C + (size_t)row * N + col) =
                make_float2(acc[mi][ni][0], acc[mi][ni][1]);
            *(float2*)(C + (size_t)(row + 8) * N + col) =
                make_float2(acc[mi][ni][2], acc[mi][ni][3]);
        }
    }
}

// ---------------------------------------------------------------------------
// Fused RMSNorm + rotary (unchanged)
// ---------------------------------------------------------------------------
__global__ __launch_bounds__(256) void rmsrot_kernel() {
    int task = blockIdx.x * 8 + (threadIdx.x >> 5);
    int lane = threadIdx.x & 31;
    int c = task & 1;
    int h = (task >> 1) % NH;
    int t = task / (2 * NH);

    float* p = g_qkv + (size_t)t * QKV_LD + c * DIMM + h * HD;
    float x0 = p[lane];
    float x1 = p[lane + 32];
    float ss = x0 * x0 + x1 * x1;
#pragma unroll
    for (int off = 16; off > 0; off >>= 1)
        ss += __shfl_xor_sync(0xffffffffu, ss, off);
    float r = rsqrtf(ss * (1.0f / 64.0f) + 1.1920928955078125e-07f);
    x0 *= r;
    x1 *= r;
    float cv = g_cos[t * 32 + lane];
    float sv = g_sin[t * 32 + lane];
    p[lane]      =  x0 * cv + x1 * sv;
    p[lane + 32] = -x0 * sv + x1 * cv;
}

// ---------------------------------------------------------------------------
// Flash attention, fp32 FFMA2 (unchanged from R7 measured version)
// ---------------------------------------------------------------------------
#define FQ 130
#define FK 68
#define FP 132
#define FLASH_SMEM ((64 * FQ + 64 * FK + 64 * FK + 64 * FP) * 4)

__global__ __launch_bounds__(256, 2) void flash_kernel() {
    extern __shared__ float sm[];
    float* QT = sm;
    float* KT = QT + 64 * FQ;
    float* Vs = KT + 64 * FK;
    float* PT = Vs + 64 * FK;

    int qb = (SEQ / 128 - 1) - blockIdx.x;
    int h  = blockIdx.y;
    int tid = threadIdx.x;
    int tx = tid & 15;
    int ty = tid >> 4;

    const float* qbase = g_qkv + (size_t)(qb * 128) * QKV_LD + h * HD;
    for (int idx = tid; idx < 128 * 64; idx += 256) {
        int t = idx >> 6, d = idx & 63;
        QT[d * FQ + t] = qbase[t * QKV_LD + d];
    }

    float m_pr[8], l_i[8];
#pragma unroll
    for (int i = 0; i < 8; i++) { m_pr[i] = -INFINITY; l_i[i] = 0.0f; }
    ull o2[4][4];
#pragma unroll
    for (int p = 0; p < 4; p++)
#pragma unroll
        for (int j = 0; j < 4; j++) o2[p][j] = 0ull;

    const float* kb = g_qkv + DIMM + h * HD;
    const float* vb = g_qkv + 2 * DIMM + h * HD;

    int ktmax = 2 * qb + 1;
    for (int kt = 0; kt <= ktmax; kt++) {
        __syncthreads();
        int t0 = kt * 64;
        for (int idx = tid; idx < 64 * 64; idx += 256) {
            int t = idx >> 6, d = idx & 63;
            size_t g = (size_t)(t0 + t) * QKV_LD + d;
            KT[d * FK + t] = kb[g];
            Vs[t * FK + d] = vb[g];
        }
        __syncthreads();

        ull s2[4][4];
#pragma unroll
        for (int p = 0; p < 4; p++)
#pragma unroll
            for (int j = 0; j < 4; j++) s2[p][j] = 0ull;
#pragma unroll 4
        for (int kk = 0; kk < 64; kk++) {
            const ull* ap = (const ull*)&QT[kk * FQ + ty * 8];
            ull a0 = ap[0], a1 = ap[1], a2 = ap[2], a3 = ap[3];
            float4 bv = *(const float4*)&KT[kk * FK + tx * 4];
            ull b0 = f2dup(bv.x), b1 = f2dup(bv.y);
            ull b2 = f2dup(bv.z), b3 = f2dup(bv.w);
            ffma2(s2[0][0], a0, b0); ffma2(s2[0][1], a0, b1);
            ffma2(s2[0][2], a0, b2); ffma2(s2[0][3], a0, b3);
            ffma2(s2[1][0], a1, b0); ffma2(s2[1][1], a1, b1);
            ffma2(s2[1][2], a1, b2); ffma2(s2[1][3], a1, b3);
            ffma2(s2[2][0], a2, b0); ffma2(s2[2][1], a2, b1);
            ffma2(s2[2][2], a2, b2); ffma2(s2[2][3], a2, b3);
            ffma2(s2[3][0], a3, b0); ffma2(s2[3][1], a3, b1);
            ffma2(s2[3][2], a3, b2); ffma2(s2[3][3], a3, b3);
        }

        bool msk = (kt >= 2 * qb);
        float pl[4][4], ph[4][4];
#pragma unroll
        for (int p = 0; p < 4; p++) {
            float slo[4], shi[4];
#pragma unroll
            for (int j = 0; j < 4; j++) {
                float lo, hi;
                f2unpack(s2[p][j], lo, hi);
                slo[j] = lo * 0.12f;
                shi[j] = hi * 0.12f;
            }
            if (msk) {
                int grl = qb * 128 + ty * 8 + 2 * p;
#pragma unroll
                for (int j = 0; j < 4; j++) {
                    int gc = t0 + tx * 4 + j;
                    if (gc > grl)     slo[j] = -3.0e38f;
                    if (gc > grl + 1) shi[j] = -3.0e38f;
                }
            }
            float ml = fmaxf(fmaxf(slo[0], slo[1]), fmaxf(slo[2], slo[3]));
            float mh = fmaxf(fmaxf(shi[0], shi[1]), fmaxf(shi[2], shi[3]));
#pragma unroll
            for (int off = 1; off < 16; off <<= 1) {
                ml = fmaxf(ml, __shfl_xor_sync(0xffffffffu, ml, off));
                mh = fmaxf(mh, __shfl_xor_sync(0xffffffffu, mh, off));
            }
            float mnl = fmaxf(m_pr[2 * p],     ml);
            float mnh = fmaxf(m_pr[2 * p + 1], mh);
            float cl = __expf(m_pr[2 * p]     - mnl);
            float ch = __expf(m_pr[2 * p + 1] - mnh);
            float sl = 0.0f, sh = 0.0f;
#pragma unroll
            for (int j = 0; j < 4; j++) {
                pl[p][j] = __expf(slo[j] - mnl); sl += pl[p][j];
                ph[p][j] = __expf(shi[j] - mnh); sh += ph[p][j];
            }
#pragma unroll
            for (int off = 1; off < 16; off <<= 1) {
                sl += __shfl_xor_sync(0xffffffffu, sl, off);
                sh += __shfl_xor_sync(0xffffffffu, sh, off);
            }
            l_i[2 * p]     = l_i[2 * p]     * cl + sl;
            l_i[2 * p + 1] = l_i[2 * p + 1] * ch + sh;
            m_pr[2 * p]     = mnl;
            m_pr[2 * p + 1] = mnh;
            ull c2 = f2pack(cl, ch);
            fmul2(o2[p][0], c2); fmul2(o2[p][1], c2);
            fmul2(o2[p][2], c2); fmul2(o2[p][3], c2);
        }

#pragma unroll
        for (int j = 0; j < 4; j++) {
            int c = tx * 4 + j;
            *(float4*)&PT[c * FP + ty * 8] =
                make_float4(pl[0][j], ph[0][j], pl[1][j], ph[1][j]);
            *(float4*)&PT[c * FP + ty * 8 + 4] =
                make_float4(pl[2][j], ph[2][j], pl[3][j], ph[3][j]);
        }
        __syncthreads();

#pragma unroll 4
        for (int kk = 0; kk < 64; kk++) {
            const ull* ap = (const ull*)&PT[kk * FP + ty * 8];
            ull a0 = ap[0], a1 = ap[1], a2 = ap[2], a3 = ap[3];
            float4 bv = *(const float4*)&Vs[kk * FK + tx * 4];
            ull b0 = f2dup(bv.x), b1 = f2dup(bv.y);
            ull b2 = f2dup(bv.z), b3 = f2dup(bv.w);
            ffma2(o2[0][0], a0, b0); ffma2(o2[0][1], a0, b1);
            ffma2(o2[0][2], a0, b2); ffma2(o2[0][3], a0, b3);
            ffma2(o2[1][0], a1, b0); ffma2(o2[1][1], a1, b1);
            ffma2(o2[1][2], a1, b2); ffma2(o2[1][3], a1, b3);
            ffma2(o2[2][0], a2, b0); ffma2(o2[2][1], a2, b1);
            ffma2(o2[2][2], a2, b2); ffma2(o2[2][3], a2, b3);
            ffma2(o2[3][0], a3, b0); ffma2(o2[3][1], a3, b1);
            ffma2(o2[3][2], a3, b2); ffma2(o2[3][3], a3, b3);
        }
    }

#pragma unroll
    for (int p = 0; p < 4; p++) {
        ull iv = f2pack(1.0f / l_i[2 * p], 1.0f / l_i[2 * p + 1]);
        fmul2(o2[p][0], iv); fmul2(o2[p][1], iv);
        fmul2(o2[p][2], iv); fmul2(o2[p][3], iv);
        float lo[4], hi[4];
#pragma unroll
        for (int j = 0; j < 4; j++) f2unpack(o2[p][j], lo[j], hi[j]);
        int t = qb * 128 + ty * 8 + 2 * p;
        *(float4*)&g_y[(size_t)t * DIMM + h * HD + tx * 4] =
            make_float4(lo[0], lo[1], lo[2], lo[3]);
        *(float4*)&g_y[(size_t)(t + 1) * DIMM + h * HD + tx * 4] =
            make_float4(hi[0], hi[1], hi[2], hi[3]);
    }
}

// ---------------------------------------------------------------------------
extern "C" void kernel_launch(void* const* d_in, const int* in_sizes, int n_in,
                              void* d_out, int out_size) {
    const float* x        = (const float*)d_in[0];   // [1,4096,768]
    const float* qkv_w    = (const float*)d_in[1];   // [3,768,768] -> [2304][768]
    const float* c_proj_w = (const float*)d_in[2];   // [768,768]
    float* out = (float*)d_out;                      // [1,4096,768]

    float *qkv_p, *y_p;
    cudaGetSymbolAddress((void**)&qkv_p, g_qkv);
    cudaGetSymbolAddress((void**)&y_p, g_y);

    cudaFuncSetAttribute(flash_kernel, cudaFuncAttributeMaxDynamicSharedMemorySize,
                         FLASH_SMEM);

    // 1. rotary tables
    rotary_tables_kernel<<<SEQ, 32>>>();
    // 2. QKV projection (tf32 warp MMA): [4096,768] x [2304,768]^T
    gemm_mma_kernel<<<dim3(QKV_LD / 128, SEQ / 128), 256>>>(
        x, qkv_w, qkv_p, SEQ, QKV_LD, DIMM);
    // 3. RMSNorm + rotary on q,k
    rmsrot_kernel<<<SEQ * NH * 2 / 8, 256>>>();
    // 4. causal flash attention (fp32 FFMA2, 128-row q blocks)
    flash_kernel<<<dim3(SEQ / 128, NH), 256, FLASH_SMEM>>>();
    // 5. output projection (tf32 warp MMA): [4096,768] x [768,768]^T
    gemm_mma_kernel<<<dim3(DIMM / 128, SEQ / 128), 256>>>(
        y_p, c_proj_w, out, SEQ, DIMM, DIMM);
}